// round 11
// baseline (speedup 1.0000x reference)
#include <cuda_runtime.h>
#include <cuda_bf16.h>

// Embedding gather: out[t,:] = e[token_ids[t],:]
// Persistent CTAs + in-thread software pipeline: issue next group's gather
// loads BEFORE draining current group's stores, so the DRAM write stream and
// the L2 read stream stay concurrently active instead of phase-alternating.

#define DIM4     256   // float4s per row
#define THREADS  256   // one float4 column per thread
#define ROWS     4     // rows per group

__global__ void __launch_bounds__(THREADS)
embedding_pipe_kernel(const int* __restrict__ token_ids,
                      const float4* __restrict__ e,    // [32000, DIM4]
                      float4* __restrict__ out,        // [n_tok, DIM4]
                      int ngroups)
{
    const int c      = threadIdx.x;
    const int stride = gridDim.x;

    int g = blockIdx.x;
    if (g >= ngroups) return;

    // Prologue: load group g.
    float4 v[ROWS];
#pragma unroll
    for (int r = 0; r < ROWS; r++) {
        const int tok = __ldg(&token_ids[g * ROWS + r]);
        v[r] = __ldg(&e[(long long)tok * DIM4 + c]);
    }

    // Steady state: prefetch g+stride, then store g.
    for (int gn = g + stride; gn < ngroups; gn += stride) {
        float4 vn[ROWS];
#pragma unroll
        for (int r = 0; r < ROWS; r++) {
            const int tok = __ldg(&token_ids[gn * ROWS + r]);
            vn[r] = __ldg(&e[(long long)tok * DIM4 + c]);
        }
        // Drain current group's stores while next group's loads are in flight.
#pragma unroll
        for (int r = 0; r < ROWS; r++)
            out[(long long)(g * ROWS + r) * DIM4 + c] = v[r];
#pragma unroll
        for (int r = 0; r < ROWS; r++)
            v[r] = vn[r];
        g = gn;
    }

    // Epilogue: store the last group.
#pragma unroll
    for (int r = 0; r < ROWS; r++)
        out[(long long)(g * ROWS + r) * DIM4 + c] = v[r];
}

extern "C" void kernel_launch(void* const* d_in, const int* in_sizes, int n_in,
                              void* d_out, int out_size)
{
    // Robust to input ordering: token_ids is the small int32 buffer,
    // e is the large fp32 table.
    const int* token_ids;
    const float4* e;
    if (n_in >= 2 && in_sizes[0] > in_sizes[1]) {
        e         = (const float4*)d_in[0];
        token_ids = (const int*)d_in[1];
    } else {
        token_ids = (const int*)d_in[0];
        e         = (const float4*)d_in[1];
    }
    float4* out = (float4*)d_out;

    const int n_tok   = out_size / (DIM4 * 4);          // 8192 (multiple of ROWS)
    const int ngroups = n_tok / ROWS;                   // 2048
    const int grid    = 444;                            // 3 CTAs/SM persistent
    embedding_pipe_kernel<<<grid, THREADS>>>(token_ids, e, out, ngroups);
}